// round 14
// baseline (speedup 1.0000x reference)
#include <cuda_runtime.h>

// Problem constants: volume (2,3,96,96,96) fp32 -> (2,3,192,192,192) fp32
#define NB 6
#define N 96
#define NO 192
#define SLICE (N * N)
#define VOL (N * N * N)

// Scratch for prefiltered spline coefficients (21.2 MB)
__device__ float g_coef[NB * VOL];

// ---------------------------------------------------------------------------
// Composite cubic B-spline prefilter: causal o anticausal == symmetric FIR
//   h[k] = sqrt(3) * p^|k|, p = sqrt(3)-2, truncated |k|<=7 (~1.3e-4/axis).
// Left mirror boundary exact via mirrored reads; right boundary via
// two-stage 8-tap causal -> clamp -> 8-tap anticausal. Taps are immediates.
// ---------------------------------------------------------------------------

// 15-tap symmetric composite, center at w[7]
__device__ __forceinline__ float dotH15(const float* w) {
    float a =               -1.7177666e-4f * w[0];
    a = fmaf( 6.4104185e-4f, w[1],  a);
    a = fmaf(-2.3923958e-3f, w[2],  a);
    a = fmaf( 8.9283344e-3f, w[3],  a);
    a = fmaf(-3.3320996e-2f, w[4],  a);
    a = fmaf( 1.2435565e-1f, w[5],  a);
    a = fmaf(-4.6410162e-1f, w[6],  a);
    a = fmaf( 1.7320508e0f,  w[7],  a);
    a = fmaf(-4.6410162e-1f, w[8],  a);
    a = fmaf( 1.2435565e-1f, w[9],  a);
    a = fmaf(-3.3320996e-2f, w[10], a);
    a = fmaf( 8.9283344e-3f, w[11], a);
    a = fmaf(-2.3923958e-3f, w[12], a);
    a = fmaf( 6.4104185e-4f, w[13], a);
    a = fmaf(-1.7177666e-4f, w[14], a);
    return a;
}

// 8-tap causal: c[i] = 6*sum_{k=0..7} p^k x[i-k]; w[7] = x[i]
__device__ __forceinline__ float dotA8(const float* w) {
    float acc =             -5.9500220e-4f * w[0];
    acc = fmaf( 2.2205777e-3f, w[1], acc);
    acc = fmaf(-8.2873086e-3f, w[2], acc);
    acc = fmaf( 3.0928657e-2f, w[3], acc);
    acc = fmaf(-1.1542732e-1f, w[4], acc);
    acc = fmaf( 4.3078062e-1f, w[5], acc);
    acc = fmaf(-1.6076952e0f,  w[6], acc);
    acc = fmaf( 6.0f,          w[7], acc);
    return acc;
}

// 8-tap anticausal: y[i] = sum_{j=0..7} (-p^{j+1}) c[i+j]; w[j] = c[i+j]
__device__ __forceinline__ float dotB8(const float* w) {
    float acc =             -2.6571710e-5f * w[7];
    acc = fmaf( 9.9170000e-5f, w[6], acc);
    acc = fmaf(-3.7009628e-4f, w[5], acc);
    acc = fmaf( 1.3812181e-3f, w[4], acc);
    acc = fmaf(-5.1547761e-3f, w[3], acc);
    acc = fmaf( 1.9237886e-2f, w[2], acc);
    acc = fmaf(-7.1796770e-2f, w[1], acc);
    acc = fmaf( 2.6794919e-1f, w[0], acc);
    return acc;
}

// ---------------------------------------------------------------------------
// Prefilter phases (R13-proven). SW = 100 row pad.
// ---------------------------------------------------------------------------
#define SW 100

// Row phase (stride 1): float4 window loads + STS.128 output.
__device__ __forceinline__ void phase_row(const float* bsrc, float* bdst, int g) {
    float yv[16];
    if (g == 0) {  // mirror: w[k] = x[k-8], x[-m] = x[m-1] reuses f[]
        float f[24];
#pragma unroll
        for (int j = 0; j < 6; ++j) {
            float4 v = *(const float4*)(bsrc + 4 * j);
            f[4 * j] = v.x; f[4 * j + 1] = v.y; f[4 * j + 2] = v.z; f[4 * j + 3] = v.w;
        }
        float w[32];
#pragma unroll
        for (int k = 1; k < 8; ++k) w[k] = f[7 - k];
#pragma unroll
        for (int k = 8; k < 32; ++k) w[k] = f[k - 8];
#pragma unroll
        for (int m = 0; m < 16; ++m) yv[m] = dotH15(w + m + 1);
    } else if (g < 5) {
        float w[32];
#pragma unroll
        for (int j = 0; j < 8; ++j) {
            float4 v = *(const float4*)(bsrc + g * 16 - 8 + 4 * j);
            w[4 * j] = v.x; w[4 * j + 1] = v.y; w[4 * j + 2] = v.z; w[4 * j + 3] = v.w;
        }
#pragma unroll
        for (int m = 0; m < 16; ++m) yv[m] = dotH15(w + m + 1);
    } else {  // right edge: 80..83 composite; 84..95 two-stage
        float xw[24];
#pragma unroll
        for (int j = 0; j < 6; ++j) {
            float4 v = *(const float4*)(bsrc + 72 + 4 * j);
            xw[4 * j] = v.x; xw[4 * j + 1] = v.y; xw[4 * j + 2] = v.z; xw[4 * j + 3] = v.w;
        }
#pragma unroll
        for (int m = 0; m < 4; ++m) yv[m] = dotH15(xw + m + 1);
        float ce[19];
#pragma unroll
        for (int j = 0; j < 12; ++j) ce[j] = dotA8(xw + 5 + j);
#pragma unroll
        for (int j = 12; j < 19; ++j) ce[j] = ce[11];
#pragma unroll
        for (int m = 0; m < 12; ++m) yv[4 + m] = dotB8(ce + m);
    }
#pragma unroll
    for (int j = 0; j < 4; ++j)
        *(float4*)(bdst + g * 16 + 4 * j) =
            make_float4(yv[4 * j], yv[4 * j + 1], yv[4 * j + 2], yv[4 * j + 3]);
}

// Column phase: scalar 30-float window at stride SS, writes at stride SD.
template <int SS, int SD, typename DstT>
__device__ __forceinline__ void phase_col(const float* bsrc, DstT* bdst, int g) {
    float yv[16];
    if (g == 0) {
        float w[30];
#pragma unroll
        for (int k = 0; k < 30; ++k) {
            int j = k - 7;
            int idx = j ^ (j >> 31);
            w[k] = bsrc[idx * SS];
        }
#pragma unroll
        for (int m = 0; m < 16; ++m) yv[m] = dotH15(w + m);
    } else if (g < 5) {
        float w[30];
#pragma unroll
        for (int k = 0; k < 30; ++k) w[k] = bsrc[(g * 16 - 7 + k) * SS];
#pragma unroll
        for (int m = 0; m < 16; ++m) yv[m] = dotH15(w + m);
    } else {
        float xw[24];
#pragma unroll
        for (int k = 0; k < 24; ++k) xw[k] = bsrc[(72 + k) * SS];
#pragma unroll
        for (int m = 0; m < 4; ++m) yv[m] = dotH15(xw + m + 1);
        float ce[19];
#pragma unroll
        for (int j = 0; j < 12; ++j) ce[j] = dotA8(xw + 5 + j);
#pragma unroll
        for (int j = 12; j < 19; ++j) ce[j] = ce[11];
#pragma unroll
        for (int m = 0; m < 12; ++m) yv[4 + m] = dotB8(ce + m);
    }
#pragma unroll
    for (int m = 0; m < 16; ++m) bdst[(g * 16 + m) * SD] = yv[m];
}

#define PF_THREADS 576
#define PF_SMEM (2 * N * SW * 4)  // 76800 B (xy only)

// ---------------------------------------------------------------------------
// Kernel A: prefilter x then y, one CTA per (b,c,z) slice.
// ---------------------------------------------------------------------------
__global__ void __launch_bounds__(PF_THREADS, 2) prefilter_xy(const float* __restrict__ in) {
    extern __shared__ float sm[];
    float* s0 = sm;
    float* s1 = sm + N * SW;
    const int slice = blockIdx.x;
    const float* src = in + (long)slice * SLICE;
    float* dst = g_coef + (long)slice * SLICE;
    const int t = threadIdx.x;
    const int g = t / N, l = t % N;

#pragma unroll
    for (int i = 0; i < 16; ++i) {
        int r = g * 16 + i;
        s0[r * SW + l] = src[r * N + l];
    }
    __syncthreads();

    phase_row(&s0[l * SW], &s1[l * SW], g);  // x: row l
    __syncthreads();
    phase_col<SW, N>(&s1[l], dst + l, g);    // y: column l -> gmem direct
}

// ---------------------------------------------------------------------------
// Kernel B: prefilter along z, smem-free streaming (R13-proven).
// ---------------------------------------------------------------------------
__global__ void __launch_bounds__(PF_THREADS) prefilter_z() {
    const int bc = blockIdx.x / N;
    const int y = blockIdx.x % N;
    float* base = g_coef + (long)bc * VOL + (long)y * N;
    const int t = threadIdx.x;
    const int g = t / N, l = t % N;
    float* col = base + l;

    float yv[16];
    if (g == 0) {
        float w[30];
#pragma unroll
        for (int k = 0; k < 30; ++k) {
            int j = k - 7;
            int idx = j ^ (j >> 31);
            w[k] = col[(long)idx * SLICE];
        }
#pragma unroll
        for (int m = 0; m < 16; ++m) yv[m] = dotH15(w + m);
    } else if (g < 5) {
        float w[30];
#pragma unroll
        for (int k = 0; k < 30; ++k) w[k] = col[(long)(g * 16 - 7 + k) * SLICE];
#pragma unroll
        for (int m = 0; m < 16; ++m) yv[m] = dotH15(w + m);
    } else {
        float xw[24];
#pragma unroll
        for (int k = 0; k < 24; ++k) xw[k] = col[(long)(72 + k) * SLICE];
#pragma unroll
        for (int m = 0; m < 4; ++m) yv[m] = dotH15(xw + m + 1);
        float ce[19];
#pragma unroll
        for (int j = 0; j < 12; ++j) ce[j] = dotA8(xw + 5 + j);
#pragma unroll
        for (int j = 12; j < 19; ++j) ce[j] = ce[11];
#pragma unroll
        for (int m = 0; m < 12; ++m) yv[4 + m] = dotB8(ce + m);
    }
    __syncthreads();  // all window values in registers -> WAR race closed
#pragma unroll
    for (int m = 0; m < 16; ++m) col[(long)(g * 16 + m) * SLICE] = yv[m];
}

// ---------------------------------------------------------------------------
// Kernel C: fused separable 3D x2 upsample, BIG z-tile.
// Coeff tile 16x8x16 (+2 halo) -> output tile 32x16x32.
// Halo amplification 2.34x (was 2.81x); 2592 CTAs; 3 CTAs/SM (75.5 KB smem).
// ---------------------------------------------------------------------------
#define CZ 16
#define CY 8
#define CX 16
#define IZ 20
#define IY 12
#define IX 20
#define SXW 36
#define UT 256

#define SXF (IZ * IY * SXW)          // 8640 floats
#define SYF (IZ * 16 * 32)           // 10240 floats
#define UPS_SMEM ((SXF + SYF) * 4)   // 75520 B

#define KA 0.00260416674427688122f
#define KB 0.0703125f
#define KC 0.31510416666666667f
#define KD 0.61197916666666663f

#define UP_EVEN(a, b_, c_, d_) fmaf(KA, (a), fmaf(KC, (b_), fmaf(KD, (c_), KB * (d_))))
#define UP_ODD(a, b_, c_, d_)  fmaf(KB, (a), fmaf(KD, (b_), fmaf(KC, (c_), KA * (d_))))

__device__ __forceinline__ float4 up_even4(float4 a, float4 b, float4 c, float4 d) {
    float4 r;
    r.x = UP_EVEN(a.x, b.x, c.x, d.x);
    r.y = UP_EVEN(a.y, b.y, c.y, d.y);
    r.z = UP_EVEN(a.z, b.z, c.z, d.z);
    r.w = UP_EVEN(a.w, b.w, c.w, d.w);
    return r;
}
__device__ __forceinline__ float4 up_odd4(float4 a, float4 b, float4 c, float4 d) {
    float4 r;
    r.x = UP_ODD(a.x, b.x, c.x, d.x);
    r.y = UP_ODD(a.y, b.y, c.y, d.y);
    r.z = UP_ODD(a.z, b.z, c.z, d.z);
    r.w = UP_ODD(a.w, b.w, c.w, d.w);
    return r;
}

__global__ void __launch_bounds__(UT, 3) upsample3d(float* __restrict__ out) {
    extern __shared__ float usm[];
    float* s_x = usm;          // [20][12][36] = 8640
    float* s_in = usm + SXF;   // [20][12][20] = 4800 (dead after stage X)
    float* s_y = usm + SXF;    // [20][16][32] = 10240 (aliases s_in)

    const int txb = blockIdx.x;            // 0..5
    const int tyb = blockIdx.y;            // 0..11
    const int tzb = blockIdx.z % (N / CZ); // 0..5
    const int bc = blockIdx.z / (N / CZ);  // 0..5
    const int t = threadIdx.x;

    const float* src = g_coef + (long)bc * VOL;
    const int gz0 = tzb * CZ - 2, gy0 = tyb * CY - 2, gx0 = txb * CX - 2;

    // Halo load with edge clamp: 4800 elems
    for (int e = t; e < IZ * IY * IX; e += UT) {
        int lx = e % IX;
        int r = e / IX;
        int ly = r % IY;
        int lz = r / IY;
        int gz = min(max(gz0 + lz, 0), N - 1);
        int gy = min(max(gy0 + ly, 0), N - 1);
        int gx = min(max(gx0 + lx, 0), N - 1);
        s_in[(lz * IY + ly) * IX + lx] = src[((long)gz * N + gy) * N + gx];
    }
    __syncthreads();

    // Stage X: 240 lines x 4 quads = 960 tasks; 8 in -> 8 out each
    for (int e = t; e < IZ * IY * 4; e += UT) {
        int q = e & 3;
        int line = e >> 2;  // lz*IY + ly
        const float* row = &s_in[line * IX + 4 * q];
        const float4 p0 = *(const float4*)row;
        const float4 p1 = *(const float4*)(row + 4);
        const float v0 = p0.x, v1 = p0.y, v2 = p0.z, v3 = p0.w;
        const float v4 = p1.x, v5 = p1.y, v6 = p1.z, v7 = p1.w;
        float4 r0, r1;
        r0.x = UP_EVEN(v0, v1, v2, v3);
        r0.y = UP_ODD(v1, v2, v3, v4);
        r0.z = UP_EVEN(v1, v2, v3, v4);
        r0.w = UP_ODD(v2, v3, v4, v5);
        r1.x = UP_EVEN(v2, v3, v4, v5);
        r1.y = UP_ODD(v3, v4, v5, v6);
        r1.z = UP_EVEN(v3, v4, v5, v6);
        r1.w = UP_ODD(v4, v5, v6, v7);
        *(float4*)&s_x[line * SXW + 8 * q] = r0;
        *(float4*)&s_x[line * SXW + 8 * q + 4] = r1;
    }
    __syncthreads();  // s_in dead -> s_y may overwrite

    // Stage Y: 20(lz) x 32(xo) = 640 tasks; window 12 -> 16 y-outputs
    for (int e = t; e < IZ * 32; e += UT) {
        const int xo = e & 31, lz = e >> 5;
        float u[IY];
#pragma unroll
        for (int h = 0; h < IY; ++h) u[h] = s_x[(lz * IY + h) * SXW + xo];
#pragma unroll
        for (int h = 0; h < CY; ++h) {
            s_y[(lz * 16 + 2 * h) * 32 + xo] = UP_EVEN(u[h], u[h + 1], u[h + 2], u[h + 3]);
            s_y[(lz * 16 + 2 * h + 1) * 32 + xo] = UP_ODD(u[h + 1], u[h + 2], u[h + 3], u[h + 4]);
        }
    }
    __syncthreads();

    // Stage Z: thread (zq, yo, xq); z-half zq covers 16 z-outputs x float4
    {
        const int xq = t & 7, yo = (t >> 3) & 15, zq = t >> 7;  // zq 0..1
        float4 u[12];
#pragma unroll
        for (int i = 0; i < 12; ++i)
            u[i] = *(const float4*)&s_y[((8 * zq + i) * 16 + yo) * 32 + 4 * xq];
        const long base_out = (((long)bc * NO + (long)tzb * (2 * CZ)) * NO +
                               (long)tyb * (2 * CY) + yo) * NO + (long)txb * (2 * CX) + 4 * xq;
#pragma unroll
        for (int h = 0; h < 8; ++h) {
            float4 o0 = up_even4(u[h], u[h + 1], u[h + 2], u[h + 3]);
            float4 o1 = up_odd4(u[h + 1], u[h + 2], u[h + 3], u[h + 4]);
            const long zo = 2 * (8 * zq + h);
            __stcs((float4*)&out[base_out + zo * NO * NO], o0);
            __stcs((float4*)&out[base_out + (zo + 1) * NO * NO], o1);
        }
    }
}

// ---------------------------------------------------------------------------
extern "C" void kernel_launch(void* const* d_in, const int* in_sizes, int n_in,
                              void* d_out, int out_size) {
    const float* in = (const float*)d_in[0];
    float* out = (float*)d_out;

    cudaFuncSetAttribute(prefilter_xy, cudaFuncAttributeMaxDynamicSharedMemorySize, PF_SMEM);
    cudaFuncSetAttribute(upsample3d, cudaFuncAttributeMaxDynamicSharedMemorySize, UPS_SMEM);

    prefilter_xy<<<NB * N, PF_THREADS, PF_SMEM>>>(in);
    prefilter_z<<<NB * N, PF_THREADS>>>();
    upsample3d<<<dim3(N / CX, N / CY, NB * (N / CZ)), UT, UPS_SMEM>>>(out);
}

// round 15
// speedup vs baseline: 1.2838x; 1.2838x over previous
#include <cuda_runtime.h>

// Problem constants: volume (2,3,96,96,96) fp32 -> (2,3,192,192,192) fp32
#define NB 6
#define N 96
#define NO 192
#define SLICE (N * N)
#define VOL (N * N * N)

// Scratch for prefiltered spline coefficients (21.2 MB)
__device__ float g_coef[NB * VOL];

// ---------------------------------------------------------------------------
// Composite cubic B-spline prefilter: causal o anticausal == symmetric FIR
//   h[k] = sqrt(3) * p^|k|, p = sqrt(3)-2, truncated |k|<=7 (~1.3e-4/axis).
// Left mirror boundary exact via mirrored reads; right boundary via
// two-stage 8-tap causal -> clamp -> 8-tap anticausal. Taps are immediates.
// ---------------------------------------------------------------------------

// 15-tap symmetric composite, center at w[7]
__device__ __forceinline__ float dotH15(const float* w) {
    float a =               -1.7177666e-4f * w[0];
    a = fmaf( 6.4104185e-4f, w[1],  a);
    a = fmaf(-2.3923958e-3f, w[2],  a);
    a = fmaf( 8.9283344e-3f, w[3],  a);
    a = fmaf(-3.3320996e-2f, w[4],  a);
    a = fmaf( 1.2435565e-1f, w[5],  a);
    a = fmaf(-4.6410162e-1f, w[6],  a);
    a = fmaf( 1.7320508e0f,  w[7],  a);
    a = fmaf(-4.6410162e-1f, w[8],  a);
    a = fmaf( 1.2435565e-1f, w[9],  a);
    a = fmaf(-3.3320996e-2f, w[10], a);
    a = fmaf( 8.9283344e-3f, w[11], a);
    a = fmaf(-2.3923958e-3f, w[12], a);
    a = fmaf( 6.4104185e-4f, w[13], a);
    a = fmaf(-1.7177666e-4f, w[14], a);
    return a;
}

// 8-tap causal: c[i] = 6*sum_{k=0..7} p^k x[i-k]; w[7] = x[i]
__device__ __forceinline__ float dotA8(const float* w) {
    float acc =             -5.9500220e-4f * w[0];
    acc = fmaf( 2.2205777e-3f, w[1], acc);
    acc = fmaf(-8.2873086e-3f, w[2], acc);
    acc = fmaf( 3.0928657e-2f, w[3], acc);
    acc = fmaf(-1.1542732e-1f, w[4], acc);
    acc = fmaf( 4.3078062e-1f, w[5], acc);
    acc = fmaf(-1.6076952e0f,  w[6], acc);
    acc = fmaf( 6.0f,          w[7], acc);
    return acc;
}

// 8-tap anticausal: y[i] = sum_{j=0..7} (-p^{j+1}) c[i+j]; w[j] = c[i+j]
__device__ __forceinline__ float dotB8(const float* w) {
    float acc =             -2.6571710e-5f * w[7];
    acc = fmaf( 9.9170000e-5f, w[6], acc);
    acc = fmaf(-3.7009628e-4f, w[5], acc);
    acc = fmaf( 1.3812181e-3f, w[4], acc);
    acc = fmaf(-5.1547761e-3f, w[3], acc);
    acc = fmaf( 1.9237886e-2f, w[2], acc);
    acc = fmaf(-7.1796770e-2f, w[1], acc);
    acc = fmaf( 2.6794919e-1f, w[0], acc);
    return acc;
}

// ---------------------------------------------------------------------------
// Prefilter phases (R13-proven). SW = 100 row pad.
// ---------------------------------------------------------------------------
#define SW 100

// Row phase (stride 1): float4 window loads + STS.128 output.
__device__ __forceinline__ void phase_row(const float* bsrc, float* bdst, int g) {
    float yv[16];
    if (g == 0) {  // mirror: w[k] = x[k-8], x[-m] = x[m-1] reuses f[]
        float f[24];
#pragma unroll
        for (int j = 0; j < 6; ++j) {
            float4 v = *(const float4*)(bsrc + 4 * j);
            f[4 * j] = v.x; f[4 * j + 1] = v.y; f[4 * j + 2] = v.z; f[4 * j + 3] = v.w;
        }
        float w[32];
#pragma unroll
        for (int k = 1; k < 8; ++k) w[k] = f[7 - k];
#pragma unroll
        for (int k = 8; k < 32; ++k) w[k] = f[k - 8];
#pragma unroll
        for (int m = 0; m < 16; ++m) yv[m] = dotH15(w + m + 1);
    } else if (g < 5) {
        float w[32];
#pragma unroll
        for (int j = 0; j < 8; ++j) {
            float4 v = *(const float4*)(bsrc + g * 16 - 8 + 4 * j);
            w[4 * j] = v.x; w[4 * j + 1] = v.y; w[4 * j + 2] = v.z; w[4 * j + 3] = v.w;
        }
#pragma unroll
        for (int m = 0; m < 16; ++m) yv[m] = dotH15(w + m + 1);
    } else {  // right edge: 80..83 composite; 84..95 two-stage
        float xw[24];
#pragma unroll
        for (int j = 0; j < 6; ++j) {
            float4 v = *(const float4*)(bsrc + 72 + 4 * j);
            xw[4 * j] = v.x; xw[4 * j + 1] = v.y; xw[4 * j + 2] = v.z; xw[4 * j + 3] = v.w;
        }
#pragma unroll
        for (int m = 0; m < 4; ++m) yv[m] = dotH15(xw + m + 1);
        float ce[19];
#pragma unroll
        for (int j = 0; j < 12; ++j) ce[j] = dotA8(xw + 5 + j);
#pragma unroll
        for (int j = 12; j < 19; ++j) ce[j] = ce[11];
#pragma unroll
        for (int m = 0; m < 12; ++m) yv[4 + m] = dotB8(ce + m);
    }
#pragma unroll
    for (int j = 0; j < 4; ++j)
        *(float4*)(bdst + g * 16 + 4 * j) =
            make_float4(yv[4 * j], yv[4 * j + 1], yv[4 * j + 2], yv[4 * j + 3]);
}

// Column phase: scalar 30-float window at stride SS, writes at stride SD.
template <int SS, int SD, typename DstT>
__device__ __forceinline__ void phase_col(const float* bsrc, DstT* bdst, int g) {
    float yv[16];
    if (g == 0) {
        float w[30];
#pragma unroll
        for (int k = 0; k < 30; ++k) {
            int j = k - 7;
            int idx = j ^ (j >> 31);
            w[k] = bsrc[idx * SS];
        }
#pragma unroll
        for (int m = 0; m < 16; ++m) yv[m] = dotH15(w + m);
    } else if (g < 5) {
        float w[30];
#pragma unroll
        for (int k = 0; k < 30; ++k) w[k] = bsrc[(g * 16 - 7 + k) * SS];
#pragma unroll
        for (int m = 0; m < 16; ++m) yv[m] = dotH15(w + m);
    } else {
        float xw[24];
#pragma unroll
        for (int k = 0; k < 24; ++k) xw[k] = bsrc[(72 + k) * SS];
#pragma unroll
        for (int m = 0; m < 4; ++m) yv[m] = dotH15(xw + m + 1);
        float ce[19];
#pragma unroll
        for (int j = 0; j < 12; ++j) ce[j] = dotA8(xw + 5 + j);
#pragma unroll
        for (int j = 12; j < 19; ++j) ce[j] = ce[11];
#pragma unroll
        for (int m = 0; m < 12; ++m) yv[4 + m] = dotB8(ce + m);
    }
#pragma unroll
    for (int m = 0; m < 16; ++m) bdst[(g * 16 + m) * SD] = yv[m];
}

#define PF_THREADS 576
#define PF_SMEM (2 * N * SW * 4)  // 76800 B (xy only)

// ---------------------------------------------------------------------------
// Kernel A: prefilter x then y, one CTA per (b,c,z) slice.
// Staging via float4 (4|96 -> each float4 stays in-row; SW=100 keeps 16B
// alignment). Row phase s0->s1; column phase writes gmem directly.
// ---------------------------------------------------------------------------
__global__ void __launch_bounds__(PF_THREADS, 2) prefilter_xy(const float* __restrict__ in) {
    extern __shared__ float sm[];
    float* s0 = sm;
    float* s1 = sm + N * SW;
    const int slice = blockIdx.x;
    const float* src = in + (long)slice * SLICE;
    float* dst = g_coef + (long)slice * SLICE;
    const int t = threadIdx.x;
    const int g = t / N, l = t % N;

    // float4 staging: 9216 floats = 2304 float4s = 576 threads x 4
#pragma unroll
    for (int k = 0; k < 4; ++k) {
        int f = (t + k * PF_THREADS) * 4;
        int r = f / N, c = f % N;
        *(float4*)&s0[r * SW + c] = *(const float4*)&src[f];
    }
    __syncthreads();

    phase_row(&s0[l * SW], &s1[l * SW], g);  // x: row l
    __syncthreads();
    phase_col<SW, N>(&s1[l], dst + l, g);    // y: column l -> gmem direct
}

// ---------------------------------------------------------------------------
// Kernel B: prefilter along z, smem-free streaming (R13-proven).
// ---------------------------------------------------------------------------
__global__ void __launch_bounds__(PF_THREADS) prefilter_z() {
    const int bc = blockIdx.x / N;
    const int y = blockIdx.x % N;
    float* base = g_coef + (long)bc * VOL + (long)y * N;
    const int t = threadIdx.x;
    const int g = t / N, l = t % N;
    float* col = base + l;

    float yv[16];
    if (g == 0) {
        float w[30];
#pragma unroll
        for (int k = 0; k < 30; ++k) {
            int j = k - 7;
            int idx = j ^ (j >> 31);
            w[k] = col[(long)idx * SLICE];
        }
#pragma unroll
        for (int m = 0; m < 16; ++m) yv[m] = dotH15(w + m);
    } else if (g < 5) {
        float w[30];
#pragma unroll
        for (int k = 0; k < 30; ++k) w[k] = col[(long)(g * 16 - 7 + k) * SLICE];
#pragma unroll
        for (int m = 0; m < 16; ++m) yv[m] = dotH15(w + m);
    } else {
        float xw[24];
#pragma unroll
        for (int k = 0; k < 24; ++k) xw[k] = col[(long)(72 + k) * SLICE];
#pragma unroll
        for (int m = 0; m < 4; ++m) yv[m] = dotH15(xw + m + 1);
        float ce[19];
#pragma unroll
        for (int j = 0; j < 12; ++j) ce[j] = dotA8(xw + 5 + j);
#pragma unroll
        for (int j = 12; j < 19; ++j) ce[j] = ce[11];
#pragma unroll
        for (int m = 0; m < 12; ++m) yv[4 + m] = dotB8(ce + m);
    }
    __syncthreads();  // all window values in registers -> WAR race closed
#pragma unroll
    for (int m = 0; m < 16; ++m) col[(long)(g * 16 + m) * SLICE] = yv[m];
}

// ---------------------------------------------------------------------------
// Kernel C: fused separable 3D x2 upsample (R13-proven sweet spot).
// Coeff tile 8x8x16 (+2 halo) -> output tile 16x16x32. 45.3 KB, 5 CTAs/SM.
// ---------------------------------------------------------------------------
#define CZ 8
#define CY 8
#define CX 16
#define IZ 12
#define IY 12
#define IX 20
#define SXW 36
#define UT 256

#define KA 0.00260416674427688122f
#define KB 0.0703125f
#define KC 0.31510416666666667f
#define KD 0.61197916666666663f

#define UP_EVEN(a, b_, c_, d_) fmaf(KA, (a), fmaf(KC, (b_), fmaf(KD, (c_), KB * (d_))))
#define UP_ODD(a, b_, c_, d_)  fmaf(KB, (a), fmaf(KD, (b_), fmaf(KC, (c_), KA * (d_))))

__device__ __forceinline__ float4 up_even4(float4 a, float4 b, float4 c, float4 d) {
    float4 r;
    r.x = UP_EVEN(a.x, b.x, c.x, d.x);
    r.y = UP_EVEN(a.y, b.y, c.y, d.y);
    r.z = UP_EVEN(a.z, b.z, c.z, d.z);
    r.w = UP_EVEN(a.w, b.w, c.w, d.w);
    return r;
}
__device__ __forceinline__ float4 up_odd4(float4 a, float4 b, float4 c, float4 d) {
    float4 r;
    r.x = UP_ODD(a.x, b.x, c.x, d.x);
    r.y = UP_ODD(a.y, b.y, c.y, d.y);
    r.z = UP_ODD(a.z, b.z, c.z, d.z);
    r.w = UP_ODD(a.w, b.w, c.w, d.w);
    return r;
}

__global__ void __launch_bounds__(UT, 5) upsample3d(float* __restrict__ out) {
    __shared__ float sm[5184 + 6144];  // 45.3 KB
    float* s_x = sm;
    float* s_in = sm + 5184;
    float* s_y = sm + 5184;

    const int txb = blockIdx.x;            // 0..5
    const int tyb = blockIdx.y;            // 0..11
    const int tzb = blockIdx.z % (N / CZ); // 0..11
    const int bc = blockIdx.z / (N / CZ);  // 0..5
    const int t = threadIdx.x;

    const float* src = g_coef + (long)bc * VOL;
    const int gz0 = tzb * CZ - 2, gy0 = tyb * CY - 2, gx0 = txb * CX - 2;

#pragma unroll
    for (int e = t; e < IZ * IY * IX; e += UT) {
        int lx = e % IX;
        int r = e / IX;
        int ly = r % IY;
        int lz = r / IY;
        int gz = min(max(gz0 + lz, 0), N - 1);
        int gy = min(max(gy0 + ly, 0), N - 1);
        int gx = min(max(gx0 + lx, 0), N - 1);
        s_in[(lz * IY + ly) * IX + lx] = src[((long)gz * N + gy) * N + gx];
    }
    __syncthreads();

    // Stage X: 144 lines x 4 quads = 576 tasks; 8 in -> 8 out each
#pragma unroll
    for (int e = t; e < IZ * IY * 4; e += UT) {
        int q = e & 3;
        int line = e >> 2;
        const float* row = &s_in[line * IX + 4 * q];
        const float4 p0 = *(const float4*)row;
        const float4 p1 = *(const float4*)(row + 4);
        const float v0 = p0.x, v1 = p0.y, v2 = p0.z, v3 = p0.w;
        const float v4 = p1.x, v5 = p1.y, v6 = p1.z, v7 = p1.w;
        float4 r0, r1;
        r0.x = UP_EVEN(v0, v1, v2, v3);
        r0.y = UP_ODD(v1, v2, v3, v4);
        r0.z = UP_EVEN(v1, v2, v3, v4);
        r0.w = UP_ODD(v2, v3, v4, v5);
        r1.x = UP_EVEN(v2, v3, v4, v5);
        r1.y = UP_ODD(v3, v4, v5, v6);
        r1.z = UP_EVEN(v3, v4, v5, v6);
        r1.w = UP_ODD(v4, v5, v6, v7);
        *(float4*)&s_x[line * SXW + 8 * q] = r0;
        *(float4*)&s_x[line * SXW + 8 * q + 4] = r1;
    }
    __syncthreads();

    // Stage Y: 384 tasks; window 12 -> 16 y-outputs
#pragma unroll
    for (int e = t; e < IZ * 32; e += UT) {
        const int xo = e & 31, lz = e >> 5;
        float u[IY];
#pragma unroll
        for (int h = 0; h < IY; ++h) u[h] = s_x[(lz * IY + h) * SXW + xo];
#pragma unroll
        for (int h = 0; h < CY; ++h) {
            s_y[(lz * 16 + 2 * h) * 32 + xo] = UP_EVEN(u[h], u[h + 1], u[h + 2], u[h + 3]);
            s_y[(lz * 16 + 2 * h + 1) * 32 + xo] = UP_ODD(u[h + 1], u[h + 2], u[h + 3], u[h + 4]);
        }
    }
    __syncthreads();

    // Stage Z: STG.128 streaming stores
    {
        const int xq = t & 7, yo = (t >> 3) & 15, zq = t >> 7;
        float4 u[8];
#pragma unroll
        for (int i = 0; i < 8; ++i)
            u[i] = *(const float4*)&s_y[((4 * zq + i) * 16 + yo) * 32 + 4 * xq];
        const long base_out = (((long)bc * NO + (long)tzb * (2 * CZ)) * NO +
                               (long)tyb * (2 * CY) + yo) * NO + (long)txb * (2 * CX) + 4 * xq;
#pragma unroll
        for (int hh = 0; hh < 4; ++hh) {
            float4 o0 = up_even4(u[hh], u[hh + 1], u[hh + 2], u[hh + 3]);
            float4 o1 = up_odd4(u[hh + 1], u[hh + 2], u[hh + 3], u[hh + 4]);
            const long zo = 2 * (4 * zq + hh);
            __stcs((float4*)&out[base_out + zo * NO * NO], o0);
            __stcs((float4*)&out[base_out + (zo + 1) * NO * NO], o1);
        }
    }
}

// ---------------------------------------------------------------------------
extern "C" void kernel_launch(void* const* d_in, const int* in_sizes, int n_in,
                              void* d_out, int out_size) {
    const float* in = (const float*)d_in[0];
    float* out = (float*)d_out;

    cudaFuncSetAttribute(prefilter_xy, cudaFuncAttributeMaxDynamicSharedMemorySize, PF_SMEM);

    prefilter_xy<<<NB * N, PF_THREADS, PF_SMEM>>>(in);
    prefilter_z<<<NB * N, PF_THREADS>>>();
    upsample3d<<<dim3(N / CX, N / CY, NB * (N / CZ)), UT>>>(out);
}

// round 16
// speedup vs baseline: 1.3079x; 1.0187x over previous
#include <cuda_runtime.h>

// Problem constants: volume (2,3,96,96,96) fp32 -> (2,3,192,192,192) fp32
#define NB 6
#define N 96
#define NO 192
#define SLICE (N * N)
#define VOL (N * N * N)

// Scratch for prefiltered spline coefficients (21.2 MB)
__device__ float g_coef[NB * VOL];

// ---------------------------------------------------------------------------
// Composite cubic B-spline prefilter: causal o anticausal == symmetric FIR
//   h[k] = sqrt(3) * p^|k|, p = sqrt(3)-2, truncated |k|<=6 (~4.7e-4/axis
//   bound; measured tracks ~0.6x). Left mirror boundary exact via mirrored
//   reads; right boundary via 7-tap causal -> clamp -> 7-tap anticausal.
// ---------------------------------------------------------------------------

// 13-tap symmetric composite, center at w[6]
__device__ __forceinline__ float dotH13(const float* w) {
    float a =                6.4104185e-4f * w[0];
    a = fmaf(-2.3923958e-3f, w[1],  a);
    a = fmaf( 8.9283344e-3f, w[2],  a);
    a = fmaf(-3.3320996e-2f, w[3],  a);
    a = fmaf( 1.2435565e-1f, w[4],  a);
    a = fmaf(-4.6410162e-1f, w[5],  a);
    a = fmaf( 1.7320508e0f,  w[6],  a);
    a = fmaf(-4.6410162e-1f, w[7],  a);
    a = fmaf( 1.2435565e-1f, w[8],  a);
    a = fmaf(-3.3320996e-2f, w[9],  a);
    a = fmaf( 8.9283344e-3f, w[10], a);
    a = fmaf(-2.3923958e-3f, w[11], a);
    a = fmaf( 6.4104185e-4f, w[12], a);
    return a;
}

// 7-tap causal: c[i] = 6*sum_{k=0..6} p^k x[i-k]; w[6] = x[i]
__device__ __forceinline__ float dotA7(const float* w) {
    float acc =              2.2205777e-3f * w[0];
    acc = fmaf(-8.2873086e-3f, w[1], acc);
    acc = fmaf( 3.0928657e-2f, w[2], acc);
    acc = fmaf(-1.1542732e-1f, w[3], acc);
    acc = fmaf( 4.3078062e-1f, w[4], acc);
    acc = fmaf(-1.6076952e0f,  w[5], acc);
    acc = fmaf( 6.0f,          w[6], acc);
    return acc;
}

// 7-tap anticausal: y[i] = sum_{j=0..6} (-p^{j+1}) c[i+j]; w[j] = c[i+j]
__device__ __forceinline__ float dotB7(const float* w) {
    float acc =              9.9170000e-5f * w[6];
    acc = fmaf(-3.7009628e-4f, w[5], acc);
    acc = fmaf( 1.3812181e-3f, w[4], acc);
    acc = fmaf(-5.1547761e-3f, w[3], acc);
    acc = fmaf( 1.9237886e-2f, w[2], acc);
    acc = fmaf(-7.1796770e-2f, w[1], acc);
    acc = fmaf( 2.6794919e-1f, w[0], acc);
    return acc;
}

// ---------------------------------------------------------------------------
// Prefilter phases. SW = 100 row pad (conflict-free both orientations).
// ---------------------------------------------------------------------------
#define SW 100

// Row phase (stride 1): aligned float4 window (w[k] = x[g*16-8+k]) + STS.128.
// 13-tap center for output m is w[m+8] -> dotH13(w + m + 2).
__device__ __forceinline__ void phase_row(const float* bsrc, float* bdst, int g) {
    float yv[16];
    if (g == 0) {  // mirror: w[k] = x[k-8]; x[-m] = x[m-1] reuses f[]
        float f[24];
#pragma unroll
        for (int j = 0; j < 6; ++j) {
            float4 v = *(const float4*)(bsrc + 4 * j);
            f[4 * j] = v.x; f[4 * j + 1] = v.y; f[4 * j + 2] = v.z; f[4 * j + 3] = v.w;
        }
        float w[32];
#pragma unroll
        for (int k = 2; k < 8; ++k) w[k] = f[7 - k];
#pragma unroll
        for (int k = 8; k < 32; ++k) w[k] = f[k - 8];
#pragma unroll
        for (int m = 0; m < 16; ++m) yv[m] = dotH13(w + m + 2);
    } else if (g < 5) {
        float w[32];
#pragma unroll
        for (int j = 0; j < 8; ++j) {
            float4 v = *(const float4*)(bsrc + g * 16 - 8 + 4 * j);
            w[4 * j] = v.x; w[4 * j + 1] = v.y; w[4 * j + 2] = v.z; w[4 * j + 3] = v.w;
        }
#pragma unroll
        for (int m = 0; m < 16; ++m) yv[m] = dotH13(w + m + 2);
    } else {  // right edge: 80..83 composite; 84..95 two-stage
        float xw[24];  // x[72..95]
#pragma unroll
        for (int j = 0; j < 6; ++j) {
            float4 v = *(const float4*)(bsrc + 72 + 4 * j);
            xw[4 * j] = v.x; xw[4 * j + 1] = v.y; xw[4 * j + 2] = v.z; xw[4 * j + 3] = v.w;
        }
#pragma unroll
        for (int m = 0; m < 4; ++m) yv[m] = dotH13(xw + m + 2);  // center xw[m+8]=x[80+m]
        float ce[18];  // c[84..95] then clamp-extension c[95]
#pragma unroll
        for (int j = 0; j < 12; ++j) ce[j] = dotA7(xw + 6 + j);  // center xw[12+j]=x[84+j]
#pragma unroll
        for (int j = 12; j < 18; ++j) ce[j] = ce[11];
#pragma unroll
        for (int m = 0; m < 12; ++m) yv[4 + m] = dotB7(ce + m);
    }
#pragma unroll
    for (int j = 0; j < 4; ++j)
        *(float4*)(bdst + g * 16 + 4 * j) =
            make_float4(yv[4 * j], yv[4 * j + 1], yv[4 * j + 2], yv[4 * j + 3]);
}

// Column phase: scalar 28-float window at stride SS, writes at stride SD.
template <int SS, int SD, typename DstT>
__device__ __forceinline__ void phase_col(const float* bsrc, DstT* bdst, int g) {
    float yv[16];
    if (g == 0) {
        float w[28];
#pragma unroll
        for (int k = 0; k < 28; ++k) {
            int j = k - 6;
            int idx = j ^ (j >> 31);  // mirror x[-m] = x[m-1]
            w[k] = bsrc[idx * SS];
        }
#pragma unroll
        for (int m = 0; m < 16; ++m) yv[m] = dotH13(w + m);
    } else if (g < 5) {
        float w[28];
#pragma unroll
        for (int k = 0; k < 28; ++k) w[k] = bsrc[(g * 16 - 6 + k) * SS];
#pragma unroll
        for (int m = 0; m < 16; ++m) yv[m] = dotH13(w + m);
    } else {
        float xw[24];
#pragma unroll
        for (int k = 0; k < 24; ++k) xw[k] = bsrc[(72 + k) * SS];
#pragma unroll
        for (int m = 0; m < 4; ++m) yv[m] = dotH13(xw + m + 2);
        float ce[18];
#pragma unroll
        for (int j = 0; j < 12; ++j) ce[j] = dotA7(xw + 6 + j);
#pragma unroll
        for (int j = 12; j < 18; ++j) ce[j] = ce[11];
#pragma unroll
        for (int m = 0; m < 12; ++m) yv[4 + m] = dotB7(ce + m);
    }
#pragma unroll
    for (int m = 0; m < 16; ++m) bdst[(g * 16 + m) * SD] = yv[m];
}

#define PF_THREADS 576
#define PF_SMEM (2 * N * SW * 4)  // 76800 B (xy only)

// ---------------------------------------------------------------------------
// Kernel A: prefilter x then y, one CTA per (b,c,z) slice.
// ---------------------------------------------------------------------------
__global__ void __launch_bounds__(PF_THREADS, 2) prefilter_xy(const float* __restrict__ in) {
    extern __shared__ float sm[];
    float* s0 = sm;
    float* s1 = sm + N * SW;
    const int slice = blockIdx.x;
    const float* src = in + (long)slice * SLICE;
    float* dst = g_coef + (long)slice * SLICE;
    const int t = threadIdx.x;
    const int g = t / N, l = t % N;

    // float4 staging: 9216 floats = 2304 float4s = 576 threads x 4
#pragma unroll
    for (int k = 0; k < 4; ++k) {
        int f = (t + k * PF_THREADS) * 4;
        int r = f / N, c = f % N;
        *(float4*)&s0[r * SW + c] = *(const float4*)&src[f];
    }
    __syncthreads();

    phase_row(&s0[l * SW], &s1[l * SW], g);  // x: row l
    __syncthreads();
    phase_col<SW, N>(&s1[l], dst + l, g);    // y: column l -> gmem direct
}

// ---------------------------------------------------------------------------
// Kernel B: prefilter along z, smem-free streaming.
// ---------------------------------------------------------------------------
__global__ void __launch_bounds__(PF_THREADS) prefilter_z() {
    const int bc = blockIdx.x / N;
    const int y = blockIdx.x % N;
    float* base = g_coef + (long)bc * VOL + (long)y * N;
    const int t = threadIdx.x;
    const int g = t / N, l = t % N;
    float* col = base + l;

    float yv[16];
    if (g == 0) {
        float w[28];
#pragma unroll
        for (int k = 0; k < 28; ++k) {
            int j = k - 6;
            int idx = j ^ (j >> 31);
            w[k] = col[(long)idx * SLICE];
        }
#pragma unroll
        for (int m = 0; m < 16; ++m) yv[m] = dotH13(w + m);
    } else if (g < 5) {
        float w[28];
#pragma unroll
        for (int k = 0; k < 28; ++k) w[k] = col[(long)(g * 16 - 6 + k) * SLICE];
#pragma unroll
        for (int m = 0; m < 16; ++m) yv[m] = dotH13(w + m);
    } else {
        float xw[24];
#pragma unroll
        for (int k = 0; k < 24; ++k) xw[k] = col[(long)(72 + k) * SLICE];
#pragma unroll
        for (int m = 0; m < 4; ++m) yv[m] = dotH13(xw + m + 2);
        float ce[18];
#pragma unroll
        for (int j = 0; j < 12; ++j) ce[j] = dotA7(xw + 6 + j);
#pragma unroll
        for (int j = 12; j < 18; ++j) ce[j] = ce[11];
#pragma unroll
        for (int m = 0; m < 12; ++m) yv[4 + m] = dotB7(ce + m);
    }
    __syncthreads();  // all window values in registers -> WAR race closed
#pragma unroll
    for (int m = 0; m < 16; ++m) col[(long)(g * 16 + m) * SLICE] = yv[m];
}

// ---------------------------------------------------------------------------
// Kernel C: fused separable 3D x2 upsample (proven sweet spot, unchanged).
// Coeff tile 8x8x16 (+2 halo) -> output tile 16x16x32. 45.3 KB, 5 CTAs/SM.
// ---------------------------------------------------------------------------
#define CZ 8
#define CY 8
#define CX 16
#define IZ 12
#define IY 12
#define IX 20
#define SXW 36
#define UT 256

#define KA 0.00260416674427688122f
#define KB 0.0703125f
#define KC 0.31510416666666667f
#define KD 0.61197916666666663f

#define UP_EVEN(a, b_, c_, d_) fmaf(KA, (a), fmaf(KC, (b_), fmaf(KD, (c_), KB * (d_))))
#define UP_ODD(a, b_, c_, d_)  fmaf(KB, (a), fmaf(KD, (b_), fmaf(KC, (c_), KA * (d_))))

__device__ __forceinline__ float4 up_even4(float4 a, float4 b, float4 c, float4 d) {
    float4 r;
    r.x = UP_EVEN(a.x, b.x, c.x, d.x);
    r.y = UP_EVEN(a.y, b.y, c.y, d.y);
    r.z = UP_EVEN(a.z, b.z, c.z, d.z);
    r.w = UP_EVEN(a.w, b.w, c.w, d.w);
    return r;
}
__device__ __forceinline__ float4 up_odd4(float4 a, float4 b, float4 c, float4 d) {
    float4 r;
    r.x = UP_ODD(a.x, b.x, c.x, d.x);
    r.y = UP_ODD(a.y, b.y, c.y, d.y);
    r.z = UP_ODD(a.z, b.z, c.z, d.z);
    r.w = UP_ODD(a.w, b.w, c.w, d.w);
    return r;
}

__global__ void __launch_bounds__(UT, 5) upsample3d(float* __restrict__ out) {
    __shared__ float sm[5184 + 6144];  // 45.3 KB
    float* s_x = sm;
    float* s_in = sm + 5184;
    float* s_y = sm + 5184;

    const int txb = blockIdx.x;            // 0..5
    const int tyb = blockIdx.y;            // 0..11
    const int tzb = blockIdx.z % (N / CZ); // 0..11
    const int bc = blockIdx.z / (N / CZ);  // 0..5
    const int t = threadIdx.x;

    const float* src = g_coef + (long)bc * VOL;
    const int gz0 = tzb * CZ - 2, gy0 = tyb * CY - 2, gx0 = txb * CX - 2;

#pragma unroll
    for (int e = t; e < IZ * IY * IX; e += UT) {
        int lx = e % IX;
        int r = e / IX;
        int ly = r % IY;
        int lz = r / IY;
        int gz = min(max(gz0 + lz, 0), N - 1);
        int gy = min(max(gy0 + ly, 0), N - 1);
        int gx = min(max(gx0 + lx, 0), N - 1);
        s_in[(lz * IY + ly) * IX + lx] = src[((long)gz * N + gy) * N + gx];
    }
    __syncthreads();

    // Stage X: 144 lines x 4 quads = 576 tasks; 8 in -> 8 out each
#pragma unroll
    for (int e = t; e < IZ * IY * 4; e += UT) {
        int q = e & 3;
        int line = e >> 2;
        const float* row = &s_in[line * IX + 4 * q];
        const float4 p0 = *(const float4*)row;
        const float4 p1 = *(const float4*)(row + 4);
        const float v0 = p0.x, v1 = p0.y, v2 = p0.z, v3 = p0.w;
        const float v4 = p1.x, v5 = p1.y, v6 = p1.z, v7 = p1.w;
        float4 r0, r1;
        r0.x = UP_EVEN(v0, v1, v2, v3);
        r0.y = UP_ODD(v1, v2, v3, v4);
        r0.z = UP_EVEN(v1, v2, v3, v4);
        r0.w = UP_ODD(v2, v3, v4, v5);
        r1.x = UP_EVEN(v2, v3, v4, v5);
        r1.y = UP_ODD(v3, v4, v5, v6);
        r1.z = UP_EVEN(v3, v4, v5, v6);
        r1.w = UP_ODD(v4, v5, v6, v7);
        *(float4*)&s_x[line * SXW + 8 * q] = r0;
        *(float4*)&s_x[line * SXW + 8 * q + 4] = r1;
    }
    __syncthreads();

    // Stage Y: 384 tasks; window 12 -> 16 y-outputs
#pragma unroll
    for (int e = t; e < IZ * 32; e += UT) {
        const int xo = e & 31, lz = e >> 5;
        float u[IY];
#pragma unroll
        for (int h = 0; h < IY; ++h) u[h] = s_x[(lz * IY + h) * SXW + xo];
#pragma unroll
        for (int h = 0; h < CY; ++h) {
            s_y[(lz * 16 + 2 * h) * 32 + xo] = UP_EVEN(u[h], u[h + 1], u[h + 2], u[h + 3]);
            s_y[(lz * 16 + 2 * h + 1) * 32 + xo] = UP_ODD(u[h + 1], u[h + 2], u[h + 3], u[h + 4]);
        }
    }
    __syncthreads();

    // Stage Z: STG.128 streaming stores
    {
        const int xq = t & 7, yo = (t >> 3) & 15, zq = t >> 7;
        float4 u[8];
#pragma unroll
        for (int i = 0; i < 8; ++i)
            u[i] = *(const float4*)&s_y[((4 * zq + i) * 16 + yo) * 32 + 4 * xq];
        const long base_out = (((long)bc * NO + (long)tzb * (2 * CZ)) * NO +
                               (long)tyb * (2 * CY) + yo) * NO + (long)txb * (2 * CX) + 4 * xq;
#pragma unroll
        for (int hh = 0; hh < 4; ++hh) {
            float4 o0 = up_even4(u[hh], u[hh + 1], u[hh + 2], u[hh + 3]);
            float4 o1 = up_odd4(u[hh + 1], u[hh + 2], u[hh + 3], u[hh + 4]);
            const long zo = 2 * (4 * zq + hh);
            __stcs((float4*)&out[base_out + zo * NO * NO], o0);
            __stcs((float4*)&out[base_out + (zo + 1) * NO * NO], o1);
        }
    }
}

// ---------------------------------------------------------------------------
extern "C" void kernel_launch(void* const* d_in, const int* in_sizes, int n_in,
                              void* d_out, int out_size) {
    const float* in = (const float*)d_in[0];
    float* out = (float*)d_out;

    cudaFuncSetAttribute(prefilter_xy, cudaFuncAttributeMaxDynamicSharedMemorySize, PF_SMEM);

    prefilter_xy<<<NB * N, PF_THREADS, PF_SMEM>>>(in);
    prefilter_z<<<NB * N, PF_THREADS>>>();
    upsample3d<<<dim3(N / CX, N / CY, NB * (N / CZ)), UT>>>(out);
}